// round 1
// baseline (speedup 1.0000x reference)
#include <cuda_runtime.h>
#include <cstddef>

// Problem constants
#define DIMC   384
#define HEADS  12
#define HD     32
#define NTOK   49
#define BWIN   4096
#define NWIN   256
#define MROWS  (BWIN * NTOK)     // 200704
#define QKVN   (3 * DIMC)        // 1152
#define QSCALE 0.17677669529663687f  // 1/sqrt(32)

// Scratch (static device allocations are allowed; cudaMalloc is not)
__device__ float g_qkv[(size_t)MROWS * QKVN];   // ~925 MB
__device__ float g_att[(size_t)MROWS * DIMC];   // ~308 MB

// ---------------------------------------------------------------------------
// SGEMM: C[M,N] = A[M,K] @ B[K,N] + bias[N], optional q-scaling for cols<DIMC
// BM=BN=128, BK=16, 256 threads, 8x8 per-thread micro-tile.
// Requires M%128==0, N%128==0, K%16==0 (true here).
// ---------------------------------------------------------------------------
template <bool QKV>
__global__ __launch_bounds__(256) void sgemm_kernel(
    const float* __restrict__ A, const float* __restrict__ B,
    const float* __restrict__ bias, float* __restrict__ C,
    int M, int N, int K)
{
    constexpr int BM = 128, BN = 128, BK = 16;
    __shared__ float As[BK][BM];   // stored transposed
    __shared__ float Bs[BK][BN];

    const int tid = threadIdx.x;
    const int tx = tid % 16;           // 0..15 -> 8 cols each
    const int ty = tid / 16;           // 0..15 -> 8 rows each
    const int bm = blockIdx.y * BM;
    const int bn = blockIdx.x * BN;

    // global-load indexing
    const int arow = tid / 4;          // 0..63 (two passes of 64 rows)
    const int acol = (tid % 4) * 4;    // 0,4,8,12
    const int brow = tid / 32;         // 0..7  (two passes of 8 rows)
    const int bcol = (tid % 32) * 4;   // 0..124

    float acc[8][8] = {};

    for (int k0 = 0; k0 < K; k0 += BK) {
        #pragma unroll
        for (int p = 0; p < 2; p++) {
            int r = arow + p * 64;
            float4 av = *(const float4*)(A + (size_t)(bm + r) * K + k0 + acol);
            As[acol + 0][r] = av.x;
            As[acol + 1][r] = av.y;
            As[acol + 2][r] = av.z;
            As[acol + 3][r] = av.w;
        }
        #pragma unroll
        for (int p = 0; p < 2; p++) {
            int r = brow + p * 8;
            float4 bv = *(const float4*)(B + (size_t)(k0 + r) * N + bn + bcol);
            *(float4*)(&Bs[r][bcol]) = bv;
        }
        __syncthreads();

        #pragma unroll
        for (int kk = 0; kk < BK; kk++) {
            float ra[8], rb[8];
            #pragma unroll
            for (int i = 0; i < 8; i += 4)
                *(float4*)(ra + i) = *(const float4*)(&As[kk][ty * 8 + i]);
            #pragma unroll
            for (int i = 0; i < 8; i += 4)
                *(float4*)(rb + i) = *(const float4*)(&Bs[kk][tx * 8 + i]);
            #pragma unroll
            for (int i = 0; i < 8; i++)
                #pragma unroll
                for (int j = 0; j < 8; j++)
                    acc[i][j] += ra[i] * rb[j];
        }
        __syncthreads();
    }

    // epilogue: bias (+ q scaling for qkv cols < DIMC)
    #pragma unroll
    for (int i = 0; i < 8; i++) {
        int row = bm + ty * 8 + i;
        #pragma unroll
        for (int j4 = 0; j4 < 8; j4 += 4) {
            float4 v;
            float* vp = (float*)&v;
            #pragma unroll
            for (int u = 0; u < 4; u++) {
                int col = bn + tx * 8 + j4 + u;
                float c = acc[i][j4 + u] + bias[col];
                if (QKV && col < DIMC) c *= QSCALE;
                vp[u] = c;
            }
            *(float4*)(C + (size_t)row * N + bn + tx * 8 + j4) = v;
        }
    }
}

// ---------------------------------------------------------------------------
// Attention: one CTA per (window b, head h).
// S = q@k^T + mask[b%NWIN] + clip(bias,±5); clip(S,±10); softmax; out = S@v
// ---------------------------------------------------------------------------
__global__ __launch_bounds__(128) void attn_kernel(
    const float* __restrict__ qkv, const float* __restrict__ mask,
    const float* __restrict__ rel_table, const int* __restrict__ rel_index,
    float* __restrict__ att_out)
{
    const int b = blockIdx.x / HEADS;
    const int h = blockIdx.x % HEADS;
    const int tid = threadIdx.x;

    __shared__ float q[NTOK][HD + 1];
    __shared__ float k[NTOK][HD + 1];
    __shared__ float v[NTOK][HD + 1];
    __shared__ float S[NTOK][NTOK + 1];

    const float* base = qkv + (size_t)b * NTOK * QKVN + h * HD;
    for (int e = tid; e < NTOK * HD; e += 128) {
        int n = e / HD, d = e % HD;
        const float* row = base + (size_t)n * QKVN;
        q[n][d] = row[d];
        k[n][d] = row[DIMC + d];
        v[n][d] = row[2 * DIMC + d];
    }
    __syncthreads();

    const int w = b % NWIN;
    const float* mrow = mask + (size_t)w * NTOK * NTOK;

    for (int e = tid; e < NTOK * NTOK; e += 128) {
        int n = e / NTOK, m = e % NTOK;
        float s = 0.f;
        #pragma unroll
        for (int d = 0; d < HD; d++) s += q[n][d] * k[m][d];
        int ridx = rel_index[e];
        float bias = rel_table[ridx * HEADS + h];
        bias = fminf(fmaxf(bias, -5.f), 5.f);
        s = s + mrow[e] + bias;
        s = fminf(fmaxf(s, -10.f), 10.f);
        S[n][m] = s;
    }
    __syncthreads();

    // row softmax (thread t handles row t)
    if (tid < NTOK) {
        float mx = -1e30f;
        #pragma unroll
        for (int m = 0; m < NTOK; m++) mx = fmaxf(mx, S[tid][m]);
        float sum = 0.f;
        #pragma unroll
        for (int m = 0; m < NTOK; m++) {
            float e = __expf(S[tid][m] - mx);
            S[tid][m] = e;
            sum += e;
        }
        float inv = 1.f / sum;
        #pragma unroll
        for (int m = 0; m < NTOK; m++) S[tid][m] *= inv;
    }
    __syncthreads();

    float* obase = att_out + (size_t)b * NTOK * DIMC + h * HD;
    for (int e = tid; e < NTOK * HD; e += 128) {
        int n = e / HD, d = e % HD;
        float s = 0.f;
        #pragma unroll
        for (int m = 0; m < NTOK; m++) s += S[n][m] * v[m][d];
        obase[(size_t)n * DIMC + d] = s;
    }
}

// ---------------------------------------------------------------------------
extern "C" void kernel_launch(void* const* d_in, const int* in_sizes, int n_in,
                              void* d_out, int out_size)
{
    const float* x         = (const float*)d_in[0];
    const float* mask      = (const float*)d_in[1];
    const float* qkv_w     = (const float*)d_in[2];
    const float* qkv_b     = (const float*)d_in[3];
    const float* proj_w    = (const float*)d_in[4];
    const float* proj_b    = (const float*)d_in[5];
    const float* rel_table = (const float*)d_in[6];
    const int*   rel_index = (const int*)d_in[7];
    float*       out       = (float*)d_out;

    float* qkvbuf = nullptr;
    float* attbuf = nullptr;
    cudaGetSymbolAddress((void**)&qkvbuf, g_qkv);
    cudaGetSymbolAddress((void**)&attbuf, g_att);

    // 1) QKV GEMM: [200704,384] @ [384,1152] (+bias, q scaled)
    {
        dim3 grid(QKVN / 128, MROWS / 128);  // (9, 1568)
        sgemm_kernel<true><<<grid, 256>>>(x, qkv_w, qkv_b, qkvbuf,
                                          MROWS, QKVN, DIMC);
    }

    // 2) Attention per (window, head)
    attn_kernel<<<BWIN * HEADS, 128>>>(qkvbuf, mask, rel_table, rel_index,
                                       attbuf);

    // 3) Proj GEMM: [200704,384] @ [384,384] (+bias) -> out
    {
        dim3 grid(DIMC / 128, MROWS / 128);  // (3, 1568)
        sgemm_kernel<false><<<grid, 256>>>(attbuf, proj_w, proj_b, out,
                                           MROWS, DIMC, DIMC);
    }
}

// round 3
// speedup vs baseline: 1.6115x; 1.6115x over previous
#include <cuda_runtime.h>
#include <cuda_bf16.h>
#include <cstdint>
#include <cstddef>

// ---------------------------------------------------------------------------
// Problem constants
// ---------------------------------------------------------------------------
#define DIMC   384
#define HEADS  12
#define HD     32
#define NTOK   49
#define BWIN   4096
#define NWIN   256
#define MROWS  (BWIN * NTOK)     // 200704
#define QKVN   (3 * DIMC)        // 1152
#define QSCALE 0.17677669529663687f  // 1/sqrt(32)

// ---------------------------------------------------------------------------
// Scratch (__device__ globals; no runtime allocation)
// ---------------------------------------------------------------------------
__device__ float g_qkv[(size_t)MROWS * QKVN];   // qkv activations fp32
__device__ float g_att[(size_t)MROWS * DIMC];   // attention output fp32
// Transposed + bf16-split weights, [N,K] layout: qkv at 0, proj after.
__device__ __nv_bfloat16 g_wt_hi[(size_t)(QKVN + DIMC) * DIMC];
__device__ __nv_bfloat16 g_wt_lo[(size_t)(QKVN + DIMC) * DIMC];

// ---------------------------------------------------------------------------
// Helpers (non-'a' ISA only: ldmatrix / mma.sync / cp.async)
// ---------------------------------------------------------------------------
__device__ __forceinline__ uint32_t smem_u32(const void* p) {
    uint32_t a;
    asm("{ .reg .u64 t; cvta.to.shared.u64 t, %1; cvt.u32.u64 %0, t; }"
        : "=r"(a) : "l"(p));
    return a;
}
__device__ __forceinline__ uint32_t sw128(uint32_t off) {
    return off ^ ((off >> 3) & 0x70);
}
__device__ __forceinline__ void ldsm4(uint32_t (&r)[4], uint32_t addr) {
    asm volatile("ldmatrix.sync.aligned.m8n8.x4.shared.b16 {%0,%1,%2,%3}, [%4];"
        : "=r"(r[0]), "=r"(r[1]), "=r"(r[2]), "=r"(r[3]) : "r"(addr));
}
__device__ __forceinline__ void mma16816(float (&d)[4], const uint32_t (&a)[4],
                                         uint32_t b0, uint32_t b1) {
    asm volatile(
        "mma.sync.aligned.m16n8k16.row.col.f32.bf16.bf16.f32 "
        "{%0,%1,%2,%3}, {%4,%5,%6,%7}, {%8,%9}, {%0,%1,%2,%3};"
        : "+f"(d[0]), "+f"(d[1]), "+f"(d[2]), "+f"(d[3])
        : "r"(a[0]), "r"(a[1]), "r"(a[2]), "r"(a[3]), "r"(b0), "r"(b1));
}
__device__ __forceinline__ void cp16(uint32_t dst, const void* src) {
    asm volatile("cp.async.cg.shared.global [%0], [%1], 16;"
                 :: "r"(dst), "l"(src));
}
#define CP_COMMIT() asm volatile("cp.async.commit_group;" ::: "memory")

__device__ __forceinline__ void cvt_hilo(const float4& x, const float4& y,
                                         uint4& hi, uint4& lo) {
    __nv_bfloat162 h0 = __floats2bfloat162_rn(x.x, x.y);
    __nv_bfloat162 h1 = __floats2bfloat162_rn(x.z, x.w);
    __nv_bfloat162 h2 = __floats2bfloat162_rn(y.x, y.y);
    __nv_bfloat162 h3 = __floats2bfloat162_rn(y.z, y.w);
    __nv_bfloat162 l0 = __floats2bfloat162_rn(x.x - __low2float(h0),
                                              x.y - __high2float(h0));
    __nv_bfloat162 l1 = __floats2bfloat162_rn(x.z - __low2float(h1),
                                              x.w - __high2float(h1));
    __nv_bfloat162 l2 = __floats2bfloat162_rn(y.x - __low2float(h2),
                                              y.y - __high2float(h2));
    __nv_bfloat162 l3 = __floats2bfloat162_rn(y.z - __low2float(h3),
                                              y.w - __high2float(h3));
    hi.x = *(uint32_t*)&h0; hi.y = *(uint32_t*)&h1;
    hi.z = *(uint32_t*)&h2; hi.w = *(uint32_t*)&h3;
    lo.x = *(uint32_t*)&l0; lo.y = *(uint32_t*)&l1;
    lo.z = *(uint32_t*)&l2; lo.w = *(uint32_t*)&l3;
}

// ---------------------------------------------------------------------------
// Weight prep: transpose W[K,N] fp32 -> Wt_hi/Wt_lo [N,K] bf16 (hi/lo split)
// ---------------------------------------------------------------------------
__global__ void prep_w_kernel(const float* __restrict__ W,
                              __nv_bfloat16* __restrict__ hi,
                              __nv_bfloat16* __restrict__ lo,
                              int K, int N) {
    int idx = blockIdx.x * blockDim.x + threadIdx.x;
    if (idx >= N * K) return;
    int n = idx / K, k = idx % K;
    float x = W[(size_t)k * N + n];
    __nv_bfloat16 h = __float2bfloat16(x);
    hi[idx] = h;
    lo[idx] = __float2bfloat16(x - __bfloat162float(h));
}

// ---------------------------------------------------------------------------
// HMMA bf16-split GEMM: C[M,N] = A[M,K] @ Wt^T + bias  (Wt is [N,K] hi/lo)
// Tile 128x128, BK=32, 256 threads (8 warps: 4m x 2n, warp tile 32x64).
// SMEM row = 128B: [hi 32xbf16 | lo 32xbf16], SW128 swizzle, double buffer.
// QKV: scale output cols < DIMC (q block) by QSCALE after bias.
// ---------------------------------------------------------------------------
#define GEMM_SMEM_BYTES (2 * 32768)   // 2 buffers x (A 16KB + B 16KB)

template <bool QKV>
__global__ __launch_bounds__(256) void mma_gemm(
    const float* __restrict__ A,
    const __nv_bfloat16* __restrict__ Bhi,
    const __nv_bfloat16* __restrict__ Blo,
    const float* __restrict__ bias,
    float* __restrict__ C, int M, int N, int K)
{
    extern __shared__ char smem[];
    const uint32_t sb = smem_u32(smem);
    const int tid  = threadIdx.x;
    const int lane = tid & 31;
    const int wid  = tid >> 5;
    const int wm   = wid & 3;          // 0..3 -> 32-row slab
    const int wn   = wid >> 2;         // 0..1 -> 64-col slab
    const int bm = blockIdx.y * 128;
    const int bn = blockIdx.x * 128;
    const int NCH = K / 32;            // 12

    const int srow = tid >> 2;         // 0..63 (two passes)
    const int skc  = tid & 3;          // 16B chunk within hi half

    float4 pa[2][2];
    float acc[2][8][4] = {};

    auto ldgA = [&](int ch) {
        const int k0 = ch * 32;
        #pragma unroll
        for (int u = 0; u < 2; u++) {
            const int r = srow + u * 64;
            const float* p = A + (size_t)(bm + r) * K + k0 + skc * 8;
            pa[u][0] = *(const float4*)p;
            pa[u][1] = *(const float4*)(p + 4);
        }
    };
    auto stsA = [&](int j) {
        #pragma unroll
        for (int u = 0; u < 2; u++) {
            const int r = srow + u * 64;
            uint4 hi, lo;
            cvt_hilo(pa[u][0], pa[u][1], hi, lo);
            char* base = smem + j * 32768;
            *(uint4*)(base + sw128((uint32_t)(r * 128 + skc * 16)))      = hi;
            *(uint4*)(base + sw128((uint32_t)(r * 128 + 64 + skc * 16))) = lo;
        }
    };
    auto cpB = [&](int ch, int j) {
        const int k0 = ch * 32;
        const uint32_t base = sb + j * 32768 + 16384;
        #pragma unroll
        for (int u = 0; u < 2; u++) {
            const int r = srow + u * 64;
            const size_t go = (size_t)(bn + r) * K + k0 + skc * 8;
            cp16(base + sw128((uint32_t)(r * 128 + skc * 16)),      Bhi + go);
            cp16(base + sw128((uint32_t)(r * 128 + 64 + skc * 16)), Blo + go);
        }
        CP_COMMIT();
    };

    auto domma = [&](int j) {
        const uint32_t sA = sb + j * 32768;
        const uint32_t sB = sA + 16384;
        #pragma unroll
        for (int ks = 0; ks < 2; ks++) {
            const int chalf = (lane >> 4);            // 0/1 -> k0-7 / k8-15
            const int chi = (2 * ks + chalf) * 16;    // hi chunk byte
            const int clo = chi + 64;                 // lo chunk byte
            uint32_t ah[2][4], al[2][4];
            #pragma unroll
            for (int mt = 0; mt < 2; mt++) {
                const int r = wm * 32 + mt * 16 + (lane & 15);
                ldsm4(ah[mt], sA + sw128((uint32_t)(r * 128 + chi)));
                ldsm4(al[mt], sA + sw128((uint32_t)(r * 128 + clo)));
            }
            uint32_t bh[4][4], bl[4][4];
            #pragma unroll
            for (int g = 0; g < 4; g++) {
                const int r = wn * 64 + g * 16 + (lane & 15);
                ldsm4(bh[g], sB + sw128((uint32_t)(r * 128 + chi)));
                ldsm4(bl[g], sB + sw128((uint32_t)(r * 128 + clo)));
            }
            #pragma unroll
            for (int mt = 0; mt < 2; mt++)
                #pragma unroll
                for (int nt = 0; nt < 8; nt++) {
                    const int g = nt >> 1, o = nt & 1;
                    mma16816(acc[mt][nt], ah[mt], bh[g][o], bh[g][o + 2]);
                    mma16816(acc[mt][nt], al[mt], bh[g][o], bh[g][o + 2]);
                    mma16816(acc[mt][nt], ah[mt], bl[g][o], bl[g][o + 2]);
                }
        }
    };

    // prologue: stage chunk 0 into buffer 0
    ldgA(0);
    cpB(0, 0);
    stsA(0);

    for (int ch = 0; ch < NCH; ch++) {
        const int j = ch & 1;
        if (ch + 1 < NCH) {
            ldgA(ch + 1);
            cpB(ch + 1, j ^ 1);
            asm volatile("cp.async.wait_group 1;" ::: "memory");
        } else {
            asm volatile("cp.async.wait_group 0;" ::: "memory");
        }
        __syncthreads();
        domma(j);
        if (ch + 1 < NCH) stsA(j ^ 1);
        __syncthreads();
    }

    // epilogue: bias (+ q scaling), fp32 store
    const float qs = (QKV && bn < DIMC) ? QSCALE : 1.0f;
    #pragma unroll
    for (int mt = 0; mt < 2; mt++) {
        const int r0 = bm + wm * 32 + mt * 16 + (lane >> 2);
        #pragma unroll
        for (int nt = 0; nt < 8; nt++) {
            const int c0 = bn + wn * 64 + nt * 8 + (lane & 3) * 2;
            const float2 bv = *(const float2*)(bias + c0);
            float2 w0, w1;
            w0.x = (acc[mt][nt][0] + bv.x) * qs;
            w0.y = (acc[mt][nt][1] + bv.y) * qs;
            w1.x = (acc[mt][nt][2] + bv.x) * qs;
            w1.y = (acc[mt][nt][3] + bv.y) * qs;
            *(float2*)(C + (size_t)r0 * N + c0)       = w0;
            *(float2*)(C + (size_t)(r0 + 8) * N + c0) = w1;
        }
    }
}

// ---------------------------------------------------------------------------
// Attention: one CTA per (window b, head h) — unchanged (passed R1)
// ---------------------------------------------------------------------------
__global__ __launch_bounds__(128) void attn_kernel(
    const float* __restrict__ qkv, const float* __restrict__ mask,
    const float* __restrict__ rel_table, const int* __restrict__ rel_index,
    float* __restrict__ att_out)
{
    const int b = blockIdx.x / HEADS;
    const int h = blockIdx.x % HEADS;
    const int tid = threadIdx.x;

    __shared__ float q[NTOK][HD + 1];
    __shared__ float k[NTOK][HD + 1];
    __shared__ float v[NTOK][HD + 1];
    __shared__ float S[NTOK][NTOK + 1];

    const float* base = qkv + (size_t)b * NTOK * QKVN + h * HD;
    for (int e = tid; e < NTOK * HD; e += 128) {
        int n = e / HD, d = e % HD;
        const float* row = base + (size_t)n * QKVN;
        q[n][d] = row[d];
        k[n][d] = row[DIMC + d];
        v[n][d] = row[2 * DIMC + d];
    }
    __syncthreads();

    const int w = b % NWIN;
    const float* mrow = mask + (size_t)w * NTOK * NTOK;

    for (int e = tid; e < NTOK * NTOK; e += 128) {
        int n = e / NTOK, m = e % NTOK;
        float s = 0.f;
        #pragma unroll
        for (int d = 0; d < HD; d++) s += q[n][d] * k[m][d];
        int ridx = rel_index[e];
        float bias = rel_table[ridx * HEADS + h];
        bias = fminf(fmaxf(bias, -5.f), 5.f);
        s = s + mrow[e] + bias;
        s = fminf(fmaxf(s, -10.f), 10.f);
        S[n][m] = s;
    }
    __syncthreads();

    if (tid < NTOK) {
        float mx = -1e30f;
        #pragma unroll
        for (int m = 0; m < NTOK; m++) mx = fmaxf(mx, S[tid][m]);
        float sum = 0.f;
        #pragma unroll
        for (int m = 0; m < NTOK; m++) {
            float e = __expf(S[tid][m] - mx);
            S[tid][m] = e;
            sum += e;
        }
        float inv = 1.f / sum;
        #pragma unroll
        for (int m = 0; m < NTOK; m++) S[tid][m] *= inv;
    }
    __syncthreads();

    float* obase = att_out + (size_t)b * NTOK * DIMC + h * HD;
    for (int e = tid; e < NTOK * HD; e += 128) {
        int n = e / HD, d = e % HD;
        float s = 0.f;
        #pragma unroll
        for (int m = 0; m < NTOK; m++) s += S[n][m] * v[m][d];
        obase[(size_t)n * DIMC + d] = s;
    }
}

// ---------------------------------------------------------------------------
extern "C" void kernel_launch(void* const* d_in, const int* in_sizes, int n_in,
                              void* d_out, int out_size)
{
    const float* x         = (const float*)d_in[0];
    const float* mask      = (const float*)d_in[1];
    const float* qkv_w     = (const float*)d_in[2];
    const float* qkv_b     = (const float*)d_in[3];
    const float* proj_w    = (const float*)d_in[4];
    const float* proj_b    = (const float*)d_in[5];
    const float* rel_table = (const float*)d_in[6];
    const int*   rel_index = (const int*)d_in[7];
    float*       out       = (float*)d_out;

    float* qkvbuf = nullptr;
    float* attbuf = nullptr;
    __nv_bfloat16* wt_hi = nullptr;
    __nv_bfloat16* wt_lo = nullptr;
    cudaGetSymbolAddress((void**)&qkvbuf, g_qkv);
    cudaGetSymbolAddress((void**)&attbuf, g_att);
    cudaGetSymbolAddress((void**)&wt_hi, g_wt_hi);
    cudaGetSymbolAddress((void**)&wt_lo, g_wt_lo);

    static int _once = []() {
        cudaFuncSetAttribute(mma_gemm<true>,
            cudaFuncAttributeMaxDynamicSharedMemorySize, GEMM_SMEM_BYTES);
        cudaFuncSetAttribute(mma_gemm<false>,
            cudaFuncAttributeMaxDynamicSharedMemorySize, GEMM_SMEM_BYTES);
        return 0;
    }();
    (void)_once;

    const size_t proj_off = (size_t)QKVN * DIMC;

    // 0) weight prep (transpose + bf16 hi/lo split) — tiny
    prep_w_kernel<<<(QKVN * DIMC + 255) / 256, 256>>>(
        qkv_w, wt_hi, wt_lo, DIMC, QKVN);
    prep_w_kernel<<<(DIMC * DIMC + 255) / 256, 256>>>(
        proj_w, wt_hi + proj_off, wt_lo + proj_off, DIMC, DIMC);

    // 1) QKV GEMM (HMMA): [200704,384] @ [384,1152]
    {
        dim3 grid(QKVN / 128, MROWS / 128);  // (9, 1568)
        mma_gemm<true><<<grid, 256, GEMM_SMEM_BYTES>>>(
            x, wt_hi, wt_lo, qkv_b, qkvbuf, MROWS, QKVN, DIMC);
    }

    // 2) Attention per (window, head)
    attn_kernel<<<BWIN * HEADS, 128>>>(qkvbuf, mask, rel_table, rel_index,
                                       attbuf);

    // 3) Proj GEMM (HMMA): [200704,384] @ [384,384] -> out
    {
        dim3 grid(DIMC / 128, MROWS / 128);  // (3, 1568)
        mma_gemm<false><<<grid, 256, GEMM_SMEM_BYTES>>>(
            attbuf, wt_hi + proj_off, wt_lo + proj_off, proj_b, out,
            MROWS, DIMC, DIMC);
    }
}

// round 5
// speedup vs baseline: 1.9135x; 1.1874x over previous
#include <cuda_runtime.h>
#include <cuda_bf16.h>
#include <cstdint>
#include <cstddef>

// ---------------------------------------------------------------------------
// Problem constants
// ---------------------------------------------------------------------------
#define DIMC   384
#define HEADS  12
#define HD     32
#define NTOK   49
#define BWIN   4096
#define NWIN   256
#define MROWS  (BWIN * NTOK)     // 200704
#define QKVN   (3 * DIMC)        // 1152
#define QSCALE 0.17677669529663687f  // 1/sqrt(32)

// ---------------------------------------------------------------------------
// Scratch (__device__ globals; no runtime allocation)
// ---------------------------------------------------------------------------
__device__ float g_qkv[(size_t)MROWS * QKVN];           // qkv activations fp32
__device__ __nv_bfloat16 g_xhi[(size_t)MROWS * DIMC];   // x split
__device__ __nv_bfloat16 g_xlo[(size_t)MROWS * DIMC];
__device__ __nv_bfloat16 g_ahi[(size_t)MROWS * DIMC];   // attn out split
__device__ __nv_bfloat16 g_alo[(size_t)MROWS * DIMC];
__device__ __nv_bfloat16 g_wt_hi[(size_t)(QKVN + DIMC) * DIMC];  // W^T split
__device__ __nv_bfloat16 g_wt_lo[(size_t)(QKVN + DIMC) * DIMC];
__device__ float g_bias[HEADS * NTOK * NTOK];           // pre-clipped rel bias

// ---------------------------------------------------------------------------
// Helpers (non-'a' ISA: ldmatrix / mma.sync / cp.async)
// ---------------------------------------------------------------------------
__device__ __forceinline__ uint32_t smem_u32(const void* p) {
    uint32_t a;
    asm("{ .reg .u64 t; cvta.to.shared.u64 t, %1; cvt.u32.u64 %0, t; }"
        : "=r"(a) : "l"(p));
    return a;
}
__device__ __forceinline__ uint32_t sw128(uint32_t off) {
    return off ^ ((off >> 3) & 0x70);
}
__device__ __forceinline__ void ldsm4(uint32_t (&r)[4], uint32_t addr) {
    asm volatile("ldmatrix.sync.aligned.m8n8.x4.shared.b16 {%0,%1,%2,%3}, [%4];"
        : "=r"(r[0]), "=r"(r[1]), "=r"(r[2]), "=r"(r[3]) : "r"(addr));
}
__device__ __forceinline__ void mma16816(float (&d)[4], const uint32_t (&a)[4],
                                         uint32_t b0, uint32_t b1) {
    asm volatile(
        "mma.sync.aligned.m16n8k16.row.col.f32.bf16.bf16.f32 "
        "{%0,%1,%2,%3}, {%4,%5,%6,%7}, {%8,%9}, {%0,%1,%2,%3};"
        : "+f"(d[0]), "+f"(d[1]), "+f"(d[2]), "+f"(d[3])
        : "r"(a[0]), "r"(a[1]), "r"(a[2]), "r"(a[3]), "r"(b0), "r"(b1));
}
__device__ __forceinline__ void cp16(uint32_t dst, const void* src) {
    asm volatile("cp.async.cg.shared.global [%0], [%1], 16;"
                 :: "r"(dst), "l"(src));
}
#define CP_COMMIT() asm volatile("cp.async.commit_group;" ::: "memory")
#define CP_WAIT1()  asm volatile("cp.async.wait_group 1;" ::: "memory")

// ---------------------------------------------------------------------------
// Prep kernels
// ---------------------------------------------------------------------------
__global__ void prep_w_kernel(const float* __restrict__ W,
                              __nv_bfloat16* __restrict__ hi,
                              __nv_bfloat16* __restrict__ lo,
                              int K, int N) {
    int idx = blockIdx.x * blockDim.x + threadIdx.x;
    if (idx >= N * K) return;
    int n = idx / K, k = idx % K;
    float x = W[(size_t)k * N + n];
    __nv_bfloat16 h = __float2bfloat16(x);
    hi[idx] = h;
    lo[idx] = __float2bfloat16(x - __bfloat162float(h));
}

__global__ void prep_x_kernel(const float* __restrict__ x,
                              __nv_bfloat16* __restrict__ hi,
                              __nv_bfloat16* __restrict__ lo, size_t n4) {
    size_t i = (size_t)blockIdx.x * blockDim.x + threadIdx.x;
    if (i >= n4) return;
    float4 xv = ((const float4*)x)[i];
    __nv_bfloat162 h0 = __floats2bfloat162_rn(xv.x, xv.y);
    __nv_bfloat162 h1 = __floats2bfloat162_rn(xv.z, xv.w);
    __nv_bfloat162 l0 = __floats2bfloat162_rn(xv.x - __low2float(h0),
                                              xv.y - __high2float(h0));
    __nv_bfloat162 l1 = __floats2bfloat162_rn(xv.z - __low2float(h1),
                                              xv.w - __high2float(h1));
    ((uint2*)hi)[i] = make_uint2(*(uint32_t*)&h0, *(uint32_t*)&h1);
    ((uint2*)lo)[i] = make_uint2(*(uint32_t*)&l0, *(uint32_t*)&l1);
}

__global__ void prep_bias_kernel(const float* __restrict__ table,
                                 const int* __restrict__ idx,
                                 float* __restrict__ out) {
    int e = blockIdx.x * blockDim.x + threadIdx.x;
    if (e >= HEADS * NTOK * NTOK) return;
    int h = e / (NTOK * NTOK), nm = e % (NTOK * NTOK);
    float b = table[idx[nm] * HEADS + h];
    out[e] = fminf(fmaxf(b, -5.f), 5.f);
}

// ---------------------------------------------------------------------------
// HMMA bf16-split GEMM (all-bf16 inputs): C = A @ Wt^T + bias
// Tile 128x128, BK=64, 3-stage cp.async pipeline, 256 threads (8 warps 4mx2n).
// Stage = 64KB: Ahi|Alo|Bhi|Blo 16KB tiles, SW128 swizzle, 128B rows (64 bf16).
// ---------------------------------------------------------------------------
#define GEMM_SMEM_BYTES (3 * 65536)

template <bool QKV>
__global__ __launch_bounds__(256, 1) void mma_gemm(
    const __nv_bfloat16* __restrict__ Ahi, const __nv_bfloat16* __restrict__ Alo,
    const __nv_bfloat16* __restrict__ Bhi, const __nv_bfloat16* __restrict__ Blo,
    const float* __restrict__ bias,
    float* __restrict__ C, int M, int N, int K)
{
    extern __shared__ char smem[];
    const uint32_t sb = smem_u32(smem);
    const int tid  = threadIdx.x;
    const int lane = tid & 31;
    const int wid  = tid >> 5;
    const int wm   = wid & 3;
    const int wn   = wid >> 2;
    const int bm = blockIdx.y * 128;
    const int bn = blockIdx.x * 128;
    const int NCH = K / 64;            // 6

    const int crow = tid >> 3;         // 0..31, +t*32
    const int cpos = tid & 7;

    auto cp_stage = [&](int s, int ch) {
        const int k0 = ch * 64;
        const uint32_t st = sb + s * 65536;
        #pragma unroll
        for (int t = 0; t < 4; t++) {
            const int row = t * 32 + crow;
            const uint32_t soff = sw128((uint32_t)(row * 128 + cpos * 16));
            const size_t ga = (size_t)(bm + row) * K + k0 + cpos * 8;
            const size_t gb = (size_t)(bn + row) * K + k0 + cpos * 8;
            cp16(st + soff,         Ahi + ga);
            cp16(st + 16384 + soff, Alo + ga);
            cp16(st + 32768 + soff, Bhi + gb);
            cp16(st + 49152 + soff, Blo + gb);
        }
    };

    float acc[2][8][4] = {};

    auto domma = [&](int s) {
        const uint32_t sA = sb + s * 65536;
        const uint32_t sB = sA + 32768;
        #pragma unroll
        for (int ks = 0; ks < 4; ks++) {
            const int cb = ks * 32 + (lane >> 4) * 16;
            uint32_t ah[2][4], al[2][4];
            #pragma unroll
            for (int mt = 0; mt < 2; mt++) {
                const int r = wm * 32 + mt * 16 + (lane & 15);
                const uint32_t o = sw128((uint32_t)(r * 128 + cb));
                ldsm4(ah[mt], sA + o);
                ldsm4(al[mt], sA + 16384 + o);
            }
            uint32_t bh[4][4], bl[4][4];
            #pragma unroll
            for (int g = 0; g < 4; g++) {
                const int r = wn * 64 + g * 16 + (lane & 15);
                const uint32_t o = sw128((uint32_t)(r * 128 + cb));
                ldsm4(bh[g], sB + o);
                ldsm4(bl[g], sB + 16384 + o);
            }
            #pragma unroll
            for (int mt = 0; mt < 2; mt++)
                #pragma unroll
                for (int nt = 0; nt < 8; nt++) {
                    const int g = nt >> 1, o = nt & 1;
                    mma16816(acc[mt][nt], ah[mt], bh[g][o], bh[g][o + 2]);
                    mma16816(acc[mt][nt], al[mt], bh[g][o], bh[g][o + 2]);
                    mma16816(acc[mt][nt], ah[mt], bl[g][o], bl[g][o + 2]);
                }
        }
    };

    // prologue: stages 0,1
    cp_stage(0, 0); CP_COMMIT();
    cp_stage(1, 1); CP_COMMIT();

    for (int ch = 0; ch < NCH; ch++) {
        const int s = ch % 3;
        CP_WAIT1();             // stage ch resident
        __syncthreads();        // all warps done with buffer (ch+2)%3's old use
        if (ch + 2 < NCH) cp_stage((ch + 2) % 3, ch + 2);
        CP_COMMIT();            // commit every iter keeps group arithmetic uniform
        domma(s);
    }

    // epilogue: bias (+ q scaling), fp32 store
    const float qs = (QKV && bn < DIMC) ? QSCALE : 1.0f;
    #pragma unroll
    for (int mt = 0; mt < 2; mt++) {
        const int r0 = bm + wm * 32 + mt * 16 + (lane >> 2);
        #pragma unroll
        for (int nt = 0; nt < 8; nt++) {
            const int c0 = bn + wn * 64 + nt * 8 + (lane & 3) * 2;
            const float2 bv = *(const float2*)(bias + c0);
            float2 w0, w1;
            w0.x = (acc[mt][nt][0] + bv.x) * qs;
            w0.y = (acc[mt][nt][1] + bv.y) * qs;
            w1.x = (acc[mt][nt][2] + bv.x) * qs;
            w1.y = (acc[mt][nt][3] + bv.y) * qs;
            *(float2*)(C + (size_t)r0 * N + c0)       = w0;
            *(float2*)(C + (size_t)(r0 + 8) * N + c0) = w1;
        }
    }
}

// ---------------------------------------------------------------------------
// Attention v2: register-tiled, CTA per (window b, head h), 128 threads.
// Thread pair per row: q row in regs, k/v via broadcast LDS.128.
// Writes bf16 hi/lo directly for the proj GEMM.
// ---------------------------------------------------------------------------
__global__ __launch_bounds__(128) void attn_kernel(
    const float* __restrict__ qkv, const float* __restrict__ mask,
    const float* __restrict__ biasArr,
    __nv_bfloat16* __restrict__ ohi, __nv_bfloat16* __restrict__ olo)
{
    const int b = blockIdx.x / HEADS;
    const int h = blockIdx.x % HEADS;
    const int tid = threadIdx.x;

    __shared__ float q[NTOK * HD];
    __shared__ float k[NTOK * HD];
    __shared__ float v[NTOK * HD];
    __shared__ float S[NTOK * NTOK];

    const float* base = qkv + (size_t)b * NTOK * QKVN + h * HD;
    for (int e = tid; e < NTOK * 8; e += 128) {
        const int n = e >> 3, j = e & 7;
        const float* row = base + (size_t)n * QKVN + j * 4;
        ((float4*)q)[e] = *(const float4*)(row);
        ((float4*)k)[e] = *(const float4*)(row + DIMC);
        ((float4*)v)[e] = *(const float4*)(row + 2 * DIMC);
    }
    __syncthreads();

    const float* mrow = mask + (size_t)(b % NWIN) * NTOK * NTOK;
    const float* brow = biasArr + h * NTOK * NTOK;

    // phase 1: S = clip(q.k + mask + bias)
    if (tid < 98) {
        const int n = tid >> 1, half = tid & 1;
        float qr[32];
        #pragma unroll
        for (int j = 0; j < 8; j++)
            *(float4*)(qr + 4 * j) = ((float4*)q)[n * 8 + j];
        const int m0 = half * 25;
        const int mc = half ? 24 : 25;
        for (int i = 0; i < mc; i++) {
            const int m = m0 + i;
            float s = 0.f;
            #pragma unroll
            for (int j = 0; j < 8; j++) {
                float4 kv = ((float4*)k)[m * 8 + j];
                s += qr[4*j]   * kv.x + qr[4*j+1] * kv.y
                   + qr[4*j+2] * kv.z + qr[4*j+3] * kv.w;
            }
            const int nm = n * NTOK + m;
            s = s + mrow[nm] + brow[nm];
            S[nm] = fminf(fmaxf(s, -10.f), 10.f);
        }
    }
    __syncthreads();

    // phase 2: row softmax
    if (tid < NTOK) {
        float* r = S + tid * NTOK;
        float mx = -1e30f;
        #pragma unroll
        for (int m = 0; m < NTOK; m++) mx = fmaxf(mx, r[m]);
        float sum = 0.f;
        #pragma unroll
        for (int m = 0; m < NTOK; m++) {
            float e = __expf(r[m] - mx);
            r[m] = e;
            sum += e;
        }
        const float inv = 1.f / sum;
        #pragma unroll
        for (int m = 0; m < NTOK; m++) r[m] *= inv;
    }
    __syncthreads();

    // phase 3: out = S@v, emit bf16 hi/lo
    if (tid < 98) {
        const int n = tid >> 1, dh = (tid & 1) * 16;
        float acc[16] = {};
        for (int m = 0; m < NTOK; m++) {
            const float p = S[n * NTOK + m];
            #pragma unroll
            for (int j = 0; j < 4; j++) {
                float4 vv = *(const float4*)(v + m * HD + dh + 4 * j);
                acc[4*j]   += p * vv.x;
                acc[4*j+1] += p * vv.y;
                acc[4*j+2] += p * vv.z;
                acc[4*j+3] += p * vv.w;
            }
        }
        const size_t o = (size_t)(b * NTOK + n) * DIMC + h * HD + dh;
        uint32_t hw[8], lw[8];
        #pragma unroll
        for (int p = 0; p < 8; p++) {
            __nv_bfloat162 hp = __floats2bfloat162_rn(acc[2*p], acc[2*p+1]);
            __nv_bfloat162 lp = __floats2bfloat162_rn(
                acc[2*p]   - __low2float(hp),
                acc[2*p+1] - __high2float(hp));
            hw[p] = *(uint32_t*)&hp;
            lw[p] = *(uint32_t*)&lp;
        }
        *(uint4*)(ohi + o)     = make_uint4(hw[0], hw[1], hw[2], hw[3]);
        *(uint4*)(ohi + o + 8) = make_uint4(hw[4], hw[5], hw[6], hw[7]);
        *(uint4*)(olo + o)     = make_uint4(lw[0], lw[1], lw[2], lw[3]);
        *(uint4*)(olo + o + 8) = make_uint4(lw[4], lw[5], lw[6], lw[7]);
    }
}

// ---------------------------------------------------------------------------
extern "C" void kernel_launch(void* const* d_in, const int* in_sizes, int n_in,
                              void* d_out, int out_size)
{
    const float* x         = (const float*)d_in[0];
    const float* mask      = (const float*)d_in[1];
    const float* qkv_w     = (const float*)d_in[2];
    const float* qkv_b     = (const float*)d_in[3];
    const float* proj_w    = (const float*)d_in[4];
    const float* proj_b    = (const float*)d_in[5];
    const float* rel_table = (const float*)d_in[6];
    const int*   rel_index = (const int*)d_in[7];
    float*       out       = (float*)d_out;

    float *qkvbuf = nullptr, *biasbuf = nullptr;
    __nv_bfloat16 *xhi, *xlo, *ahi, *alo, *wt_hi, *wt_lo;
    cudaGetSymbolAddress((void**)&qkvbuf, g_qkv);
    cudaGetSymbolAddress((void**)&biasbuf, g_bias);
    cudaGetSymbolAddress((void**)&xhi, g_xhi);
    cudaGetSymbolAddress((void**)&xlo, g_xlo);
    cudaGetSymbolAddress((void**)&ahi, g_ahi);
    cudaGetSymbolAddress((void**)&alo, g_alo);
    cudaGetSymbolAddress((void**)&wt_hi, g_wt_hi);
    cudaGetSymbolAddress((void**)&wt_lo, g_wt_lo);

    static int _once = []() {
        cudaFuncSetAttribute(mma_gemm<true>,
            cudaFuncAttributeMaxDynamicSharedMemorySize, GEMM_SMEM_BYTES);
        cudaFuncSetAttribute(mma_gemm<false>,
            cudaFuncAttributeMaxDynamicSharedMemorySize, GEMM_SMEM_BYTES);
        return 0;
    }();
    (void)_once;

    const size_t proj_off = (size_t)QKVN * DIMC;

    // 0) preps
    prep_w_kernel<<<(QKVN * DIMC + 255) / 256, 256>>>(
        qkv_w, wt_hi, wt_lo, DIMC, QKVN);
    prep_w_kernel<<<(DIMC * DIMC + 255) / 256, 256>>>(
        proj_w, wt_hi + proj_off, wt_lo + proj_off, DIMC, DIMC);
    prep_bias_kernel<<<(HEADS * NTOK * NTOK + 255) / 256, 256>>>(
        rel_table, rel_index, biasbuf);
    {
        const size_t n4 = (size_t)MROWS * DIMC / 4;
        prep_x_kernel<<<(unsigned)((n4 + 255) / 256), 256>>>(x, xhi, xlo, n4);
    }

    // 1) QKV GEMM (HMMA 3-stage): [200704,384] @ [384,1152]
    {
        dim3 grid(QKVN / 128, MROWS / 128);  // (9, 1568)
        mma_gemm<true><<<grid, 256, GEMM_SMEM_BYTES>>>(
            xhi, xlo, wt_hi, wt_lo, qkv_b, qkvbuf, MROWS, QKVN, DIMC);
    }

    // 2) Attention per (window, head) -> bf16 hi/lo
    attn_kernel<<<BWIN * HEADS, 128>>>(qkvbuf, mask, biasbuf, ahi, alo);

    // 3) Proj GEMM: [200704,384] @ [384,384] -> out
    {
        dim3 grid(DIMC / 128, MROWS / 128);  // (3, 1568)
        mma_gemm<false><<<grid, 256, GEMM_SMEM_BYTES>>>(
            ahi, alo, wt_hi + proj_off, wt_lo + proj_off, proj_b, out,
            MROWS, DIMC, DIMC);
    }
}